// round 2
// baseline (speedup 1.0000x reference)
#include <cuda_runtime.h>

// Global accumulators (scratch via __device__ globals per harness rules).
// g_acc[0] = sum over all elements of x^2
// g_acc[1] = sum over all (b,c,x,y) rows of (sum_z x)^2 + (sum_z (-1)^z x)^2
__device__ double g_acc[2];

__global__ void zero_acc_kernel() {
    g_acc[0] = 0.0;
    g_acc[1] = 0.0;
}

// One warp per z-row of 128 floats. Each lane loads one float4 (lane*4 .. lane*4+3),
// fully coalesced: 32 lanes * 16B = 512B per warp = one row.
__global__ void row_reduce_kernel(const float4* __restrict__ x4) {
    const int lane = threadIdx.x & 31;
    const int wib  = threadIdx.x >> 5;            // warp-in-block (0..7)
    const long long warp_global = ((long long)blockIdx.x * blockDim.x + threadIdx.x) >> 5;

    const float4 v = x4[warp_global * 32 + lane];

    // z indices covered by this lane: 4*lane + {0,1,2,3} -> signs +,-,+,-
    float s0 = v.x + v.y + v.z + v.w;             // plain z-sum
    float s1 = v.x - v.y + v.z - v.w;             // alternating z-sum
    float e  = v.x * v.x + v.y * v.y + v.z * v.z + v.w * v.w;

    // pairwise warp reduction (float; log-depth => tiny error)
    #pragma unroll
    for (int o = 16; o > 0; o >>= 1) {
        s0 += __shfl_xor_sync(0xffffffffu, s0, o);
        s1 += __shfl_xor_sync(0xffffffffu, s1, o);
        e  += __shfl_xor_sync(0xffffffffu, e,  o);
    }

    __shared__ double sh_e[8];
    __shared__ double sh_s[8];
    if (lane == 0) {
        sh_e[wib] = (double)e;
        sh_s[wib] = (double)s0 * (double)s0 + (double)s1 * (double)s1;
    }
    __syncthreads();

    if (threadIdx.x == 0) {
        double te = 0.0, ts = 0.0;
        #pragma unroll
        for (int i = 0; i < 8; i++) { te += sh_e[i]; ts += sh_s[i]; }
        atomicAdd(&g_acc[0], te);
        atomicAdd(&g_acc[1], ts);
    }
}

// Epilogue: combine accumulators into the final scalar loss.
//
// Derivation: k_mag is built from NORMALIZED fft frequencies (<= sqrt(3)/2
// ~ 0.866) while k_bins = linspace(0, 32, 32) has spacing 32/31 ~ 1.032,
// so searchsorted(..., 'right') maps EVERY point to bin index 1:
//   spectrum[1] = E_half / (128*128*65 * B), all other bins 0.
//
// E_half (rfft half-grid energy) via Parseval:
//   E_half = 0.5 * (128^3 * sum(x^2) + 128^2 * sum(s0^2 + s1^2))
// where s0 = sum_z x, s1 = sum_z (-1)^z x per (b,c,x,y) row (the kz=0 and
// kz=Nyquist planes are 2D FFTs of those sums).
//
// decay loss: k_max = min(128,128,65)//2 = 32, start = 32//4+1 = 9.
// spectrum[9:] is all-zero => actual_n = 0 => data-independent constant:
//   mean_{k=9..31} ( (k^{-5/3} / (9^{-5/3} + 1e-8))^2 )   (23 terms)
// cascade loss: diff has 31 entries, only diff[0]=spectrum[1] is positive:
//   cascade = spectrum[1] / 31.
__global__ void finalize_kernel(float* __restrict__ out) {
    const double E  = g_acc[0];
    const double S  = g_acc[1];

    const double Ntot   = 2097152.0;        // 128^3
    const double Nplane = 16384.0;          // 128^2
    const double e_half = 0.5 * (Ntot * E + Nplane * S);

    const double npts = 128.0 * 128.0 * 65.0;   // rfft grid points
    const double B    = 4.0;
    const double spectrum1 = e_half / (npts * B);

    // data-independent decay loss, k = 9 .. 31
    const double p = -5.0 / 3.0;
    const double denom = pow(9.0, p) + 1e-8;
    double acc = 0.0;
    for (int k = 9; k < 32; k++) {
        double en = pow((double)k, p) / denom;
        acc += en * en;
    }
    const double decay_loss = acc / 23.0;

    const double cascade_loss = spectrum1 / 31.0;

    out[0] = (float)(0.01 * decay_loss + 0.001 * cascade_loss);
}

extern "C" void kernel_launch(void* const* d_in, const int* in_sizes, int n_in,
                              void* d_out, int out_size) {
    const float4* x4 = (const float4*)d_in[0];
    float* out = (float*)d_out;

    const long long n = in_sizes[0];          // 4*3*128*128*128 = 25165824
    const long long rows = n / 128;           // 196608 z-rows
    const int threads = 256;                  // 8 warps/block, 1 row per warp
    const long long blocks = rows / 8;        // 24576

    zero_acc_kernel<<<1, 1>>>();
    row_reduce_kernel<<<(unsigned)blocks, threads>>>(x4);
    finalize_kernel<<<1, 1>>>(out);
}

// round 3
// speedup vs baseline: 1.7690x; 1.7690x over previous
#include <cuda_runtime.h>

// ---- problem constants (shapes are fixed by the dataset) ----
#define NROWS      196608LL   // 4*3*128*128 z-rows of 128 floats
#define WARPS_PB   8
#define ROWS_PW    16
#define NBLOCKS    1536       // NROWS / (WARPS_PB * ROWS_PW)

// Per-block partials: .x = sum(x^2), .y = sum over rows of (sum_z x)^2 + (sum_z (-1)^z x)^2
// Every slot is written on every launch -> no zero-init kernel needed, deterministic.
__device__ double2 g_part[NBLOCKS];

// One warp handles 16 consecutive z-rows (8 KB contiguous). Each lane loads one
// float4 per row (coalesced 512B/warp/row). Fully unrolled -> 16 independent
// LDG.128 in flight per thread (high MLP), shuffles overlap with memory.
__global__ void __launch_bounds__(256) row_reduce_kernel(const float4* __restrict__ x4) {
    const int lane = threadIdx.x & 31;
    const int wib  = threadIdx.x >> 5;
    const long long warp_id = (long long)blockIdx.x * WARPS_PB + wib;
    const float4* __restrict__ base = x4 + warp_id * (ROWS_PW * 32) + lane;

    float e  = 0.0f;   // per-lane sum of squares
    float ss = 0.0f;   // per-warp sum of row-sum squares (same in all lanes)

    #pragma unroll
    for (int r = 0; r < ROWS_PW; r++) {
        const float4 v = base[r * 32];
        e += v.x * v.x + v.y * v.y + v.z * v.z + v.w * v.w;
        // z = 4*lane + {0,1,2,3} -> alternating signs +,-,+,-
        float s0 = v.x + v.y + v.z + v.w;
        float s1 = v.x - v.y + v.z - v.w;
        #pragma unroll
        for (int o = 16; o > 0; o >>= 1) {
            s0 += __shfl_xor_sync(0xffffffffu, s0, o);
            s1 += __shfl_xor_sync(0xffffffffu, s1, o);
        }
        ss += s0 * s0 + s1 * s1;
    }

    #pragma unroll
    for (int o = 16; o > 0; o >>= 1)
        e += __shfl_xor_sync(0xffffffffu, e, o);

    __shared__ float sh_e[WARPS_PB];
    __shared__ float sh_s[WARPS_PB];
    if (lane == 0) { sh_e[wib] = e; sh_s[wib] = ss; }
    __syncthreads();

    if (threadIdx.x == 0) {
        double te = 0.0, ts = 0.0;
        #pragma unroll
        for (int i = 0; i < WARPS_PB; i++) { te += (double)sh_e[i]; ts += (double)sh_s[i]; }
        g_part[blockIdx.x] = make_double2(te, ts);
    }
}

// Reduce 1536 partials + compute the final scalar loss.
//
// Math (derived from the reference):
//   k_mag uses NORMALIZED fft frequencies (<= sqrt(3)/2), k_bins = linspace(0,32,32)
//   (k_max = min(128,128,65)//2 = 32), spacing 32/31 > sqrt(3)/2, so searchsorted
//   puts EVERY point into bin 1: spectrum[1] = E_half/(128*128*65*B), rest 0.
//   E_half via Parseval: 0.5*(128^3*sum(x^2) + 128^2*sum(s0^2+s1^2)) where s0/s1
//   are plain/alternating z-sums (kz=0 and kz=Nyquist planes = 2D FFTs of those).
//   decay loss: start = 32//4+1 = 9; spectrum[9:] == 0 => data-independent
//   constant mean_{k=9..31}((k^{-5/3}/(9^{-5/3}+1e-8))^2).
//   cascade loss: spectrum[1]/31.
__global__ void __launch_bounds__(256) finalize_kernel(float* __restrict__ out) {
    const int tid = threadIdx.x;
    double te = 0.0, ts = 0.0;
    #pragma unroll
    for (int i = 0; i < NBLOCKS / 256; i++) {
        const double2 p = g_part[tid + i * 256];
        te += p.x; ts += p.y;
    }
    // warp reduce in double
    #pragma unroll
    for (int o = 16; o > 0; o >>= 1) {
        te += __shfl_xor_sync(0xffffffffu, te, o);
        ts += __shfl_xor_sync(0xffffffffu, ts, o);
    }
    __shared__ double sh_e[8];
    __shared__ double sh_s[8];
    const int lane = tid & 31, wib = tid >> 5;
    if (lane == 0) { sh_e[wib] = te; sh_s[wib] = ts; }
    __syncthreads();

    if (tid == 0) {
        double E = 0.0, S = 0.0;
        #pragma unroll
        for (int i = 0; i < 8; i++) { E += sh_e[i]; S += sh_s[i]; }

        const double Ntot   = 2097152.0;   // 128^3
        const double Nplane = 16384.0;     // 128^2
        const double e_half = 0.5 * (Ntot * E + Nplane * S);
        const double spectrum1 = e_half / (128.0 * 128.0 * 65.0 * 4.0);

        const double p = -5.0 / 3.0;
        const double denom = pow(9.0, p) + 1e-8;
        double acc = 0.0;
        for (int k = 9; k < 32; k++) {
            double en = pow((double)k, p) / denom;
            acc += en * en;
        }
        const double decay_loss   = acc / 23.0;
        const double cascade_loss = spectrum1 / 31.0;

        out[0] = (float)(0.01 * decay_loss + 0.001 * cascade_loss);
    }
}

extern "C" void kernel_launch(void* const* d_in, const int* in_sizes, int n_in,
                              void* d_out, int out_size) {
    const float4* x4 = (const float4*)d_in[0];
    float* out = (float*)d_out;

    row_reduce_kernel<<<NBLOCKS, 256>>>(x4);
    finalize_kernel<<<1, 256>>>(out);
}

// round 4
// speedup vs baseline: 7.6341x; 4.3155x over previous
#include <cuda_runtime.h>
#include <math.h>

// ---- problem constants (shapes fixed by the dataset) ----
#define NROWS      196608LL   // 4*3*128*128 z-rows of 128 floats
#define WARPS_PB   8
#define ROWS_PW    16
#define NBLOCKS    1536       // NROWS / (WARPS_PB * ROWS_PW)

// Per-block partials: .x = sum(x^2), .y = sum over rows of (sum_z x)^2 + (sum_z (-1)^z x)^2
__device__ double2 g_part[NBLOCKS];
__device__ unsigned int g_ticket;   // zero-initialized; last block resets it -> replay-safe

// One warp handles 16 consecutive z-rows (8 KB contiguous). Each lane loads one
// float4 per row (coalesced 512B/warp/row), fully unrolled -> high MLP.
// Final loss = c0 + c1*E + c2*S, coefficients precomputed on host:
//   k_mag uses NORMALIZED fft freqs (<= sqrt(3)/2); k_bins = linspace(0,32,32)
//   (k_max = min(128,128,65)//2 = 32) has spacing 32/31 > sqrt(3)/2, so every
//   point lands in bin 1: spectrum[1] = E_half/(128*128*65*B), rest 0.
//   E_half via Parseval: 0.5*(128^3*sum(x^2) + 128^2*sum(s0^2+s1^2)), s0/s1 =
//   plain/alternating z-sums (kz=0 and kz=Nyquist planes are 2D FFTs of those).
//   decay loss (spectrum[9:]==0) is the data-independent constant inside c0;
//   cascade loss = spectrum[1]/31.
__global__ void __launch_bounds__(256) spectral_kernel(const float4* __restrict__ x4,
                                                       float* __restrict__ out,
                                                       double c0, double c1, double c2) {
    const int lane = threadIdx.x & 31;
    const int wib  = threadIdx.x >> 5;
    const long long warp_id = (long long)blockIdx.x * WARPS_PB + wib;
    const float4* __restrict__ base = x4 + warp_id * (ROWS_PW * 32) + lane;

    float e  = 0.0f;   // per-lane sum of squares
    float ss = 0.0f;   // per-warp sum of row-sum squares

    #pragma unroll
    for (int r = 0; r < ROWS_PW; r++) {
        const float4 v = base[r * 32];
        e += v.x * v.x + v.y * v.y + v.z * v.z + v.w * v.w;
        // z = 4*lane + {0,1,2,3} -> alternating signs +,-,+,-
        float s0 = v.x + v.y + v.z + v.w;
        float s1 = v.x - v.y + v.z - v.w;
        #pragma unroll
        for (int o = 16; o > 0; o >>= 1) {
            s0 += __shfl_xor_sync(0xffffffffu, s0, o);
            s1 += __shfl_xor_sync(0xffffffffu, s1, o);
        }
        ss += s0 * s0 + s1 * s1;
    }

    #pragma unroll
    for (int o = 16; o > 0; o >>= 1)
        e += __shfl_xor_sync(0xffffffffu, e, o);

    __shared__ float sh_e[WARPS_PB];
    __shared__ float sh_s[WARPS_PB];
    if (lane == 0) { sh_e[wib] = e; sh_s[wib] = ss; }
    __syncthreads();

    __shared__ bool is_last;
    if (threadIdx.x == 0) {
        double te = 0.0, ts = 0.0;
        #pragma unroll
        for (int i = 0; i < WARPS_PB; i++) { te += (double)sh_e[i]; ts += (double)sh_s[i]; }
        g_part[blockIdx.x] = make_double2(te, ts);
        __threadfence();                                   // partial visible before ticket
        unsigned int t = atomicAdd(&g_ticket, 1u);
        is_last = (t == NBLOCKS - 1);
    }
    __syncthreads();

    if (!is_last) return;

    // ---- last block: reduce all partials (hot in L2) and finalize ----
    const int tid = threadIdx.x;
    double te = 0.0, ts = 0.0;
    #pragma unroll
    for (int i = 0; i < NBLOCKS / 256; i++) {
        const double2 p = g_part[tid + i * 256];
        te += p.x; ts += p.y;
    }
    #pragma unroll
    for (int o = 16; o > 0; o >>= 1) {
        te += __shfl_xor_sync(0xffffffffu, te, o);
        ts += __shfl_xor_sync(0xffffffffu, ts, o);
    }
    __shared__ double fh_e[8];
    __shared__ double fh_s[8];
    if (lane == 0) { fh_e[wib] = te; fh_s[wib] = ts; }
    __syncthreads();

    if (tid == 0) {
        double E = 0.0, S = 0.0;
        #pragma unroll
        for (int i = 0; i < 8; i++) { E += fh_e[i]; S += fh_s[i]; }
        out[0] = (float)(c0 + c1 * E + c2 * S);
        g_ticket = 0;                                      // reset for next graph replay
    }
}

extern "C" void kernel_launch(void* const* d_in, const int* in_sizes, int n_in,
                              void* d_out, int out_size) {
    const float4* x4 = (const float4*)d_in[0];
    float* out = (float*)d_out;

    // ---- host-side constant folding (captured as kernel args) ----
    // decay loss: mean_{k=9..31} ((k^{-5/3}/(9^{-5/3}+1e-8))^2)
    const double p = -5.0 / 3.0;
    const double denom = pow(9.0, p) + 1e-8;
    double acc = 0.0;
    for (int k = 9; k < 32; k++) {
        double en = pow((double)k, p) / denom;
        acc += en * en;
    }
    const double decay_loss = acc / 23.0;

    // spectrum1 = 0.5*(128^3*E + 128^2*S) / (128*128*65*4); cascade = spectrum1/31
    const double inv_npts = 1.0 / (128.0 * 128.0 * 65.0 * 4.0);
    const double c_casc   = 0.001 / 31.0;
    const double c0 = 0.01 * decay_loss;
    const double c1 = c_casc * 0.5 * 2097152.0 * inv_npts;   // multiplies E = sum(x^2)
    const double c2 = c_casc * 0.5 * 16384.0   * inv_npts;   // multiplies S = sum(s0^2+s1^2)

    spectral_kernel<<<NBLOCKS, 256>>>(x4, out, c0, c1, c2);
}